// round 17
// baseline (speedup 1.0000x reference)
#include <cuda_runtime.h>
#include <cuda_fp16.h>
#include <cstdint>
#include <math.h>

#define THREADS  256
#define PPB      128
#define NBLOCKS  2048

// ---- smem: output staging only ----
#define STG_W     132
#define SM_WORDS  (64 * STG_W)
#define SM_BYTES  (SM_WORDS * 4)            // 33792 B -> 2 CTAs/SM

// weight fragment buffers in global scratch (L1/L2-resident, written by prep)
__device__ __align__(16) uint32_t g_w1h[4096];   // W1 fp16 B-frags [kk(4)][ntile(16)][lane(32)][2]
__device__ __align__(16) uint32_t g_wfh[6144];   // Wf fp16 B-frags [kc(12)][ntile(8)][lane(32)][2]

__device__ __forceinline__ uint32_t pack_h2(float lo, float hi) {
    __half2 h = __floats2half2_rn(lo, hi);
    return *reinterpret_cast<uint32_t*>(&h);
}
// fp16 m16n8k16, fp32 accumulate
__device__ __forceinline__ void mma16(float d[4], const uint32_t a[4],
                                      uint32_t b0, uint32_t b1) {
    asm volatile(
        "mma.sync.aligned.m16n8k16.row.col.f32.f16.f16.f32 "
        "{%0,%1,%2,%3}, {%4,%5,%6,%7}, {%8,%9}, {%0,%1,%2,%3};"
        : "+f"(d[0]), "+f"(d[1]), "+f"(d[2]), "+f"(d[3])
        : "r"(a[0]), "r"(a[1]), "r"(a[2]), "r"(a[3]), "r"(b0), "r"(b1));
}
// fp16 m16n8k16, fp16 accumulate (packed half2: reg0=row g, reg1=row g+8)
__device__ __forceinline__ void mma16h(uint32_t d[2], const uint32_t a[4],
                                       uint32_t b0, uint32_t b1) {
    asm volatile(
        "mma.sync.aligned.m16n8k16.row.col.f16.f16.f16.f16 "
        "{%0,%1}, {%2,%3,%4,%5}, {%6,%7}, {%0,%1};"
        : "+r"(d[0]), "+r"(d[1])
        : "r"(a[0]), "r"(a[1]), "r"(a[2]), "r"(a[3]), "r"(b0), "r"(b1));
}
__device__ __forceinline__ float tanh_f(float z) {
    float t;
    asm("tanh.approx.f32 %0, %1;" : "=f"(t) : "f"(z));
    return t;
}
__device__ __forceinline__ uint32_t tanh_h2(uint32_t z) {
    uint32_t t;
    asm("tanh.approx.f16x2 %0, %1;" : "=r"(t) : "r"(z));
    return t;
}
__device__ __forceinline__ float sigmoid_t(float v) {
    return fmaf(0.5f, tanh_f(0.5f * v), 0.5f);
}
// packed gelu(h) * w2 + sp
__device__ __forceinline__ __half2 gelu_w2_h2(__half2 h, __half2 w2, __half2 sp) {
    const __half2 c3 = __float2half2_rn(0.03528f);
    const __half2 c1 = __float2half2_rn(0.7988f);
    const __half2 ch = __float2half2_rn(0.5f);
    __half2 z  = __hmul2(h, __hfma2(__hmul2(h, h), c3, c1));
    uint32_t zt = tanh_h2(*reinterpret_cast<uint32_t*>(&z));
    __half2 th = *reinterpret_cast<__half2*>(&zt);
    __half2 hh = __hmul2(h, ch);
    __half2 gl = __hfma2(hh, th, hh);
    return __hfma2(gl, w2, sp);
}

__global__ void __launch_bounds__(512)
prep_w(const float* __restrict__ W1, const float* __restrict__ Wf) {
    int i = blockIdx.x * 512 + threadIdx.x;
    if (i < 4096) {
        int w = i & 1, lane = (i >> 1) & 31, ntile = (i >> 6) & 15, kk = i >> 10;
        int g = lane >> 2, tig = lane & 3;
        int n = ntile * 8 + g;
        int k = kk * 16 + 2 * tig + 8 * w;
        int row = k + ((n >= 64) ? 64 : 0);
        int col = n & 63;
        g_w1h[i] = pack_h2(W1[row * 64 + col], W1[(row + 1) * 64 + col]);
    } else if (i < 4096 + 6144) {
        int j = i - 4096;
        int w = j & 1, lane = (j >> 1) & 31, ntile = (j >> 6) & 7, kc = j >> 9;
        int g = lane >> 2, tig = lane & 3;
        int n = ntile * 8 + g;
        int k = kc * 16 + 2 * tig + 8 * w;
        g_wfh[j] = pack_h2(Wf[k * 64 + n], Wf[(k + 1) * 64 + n]);
    }
}

__global__ void __launch_bounds__(THREADS, 2)
dig_mma15(const float* __restrict__ deg,
          const float* __restrict__ b1,
          const float* __restrict__ W2,
          const float* __restrict__ b2,
          const float* __restrict__ bf,
          float* __restrict__ out)
{
    extern __shared__ float sm[];
    float* stg = sm;                 // [64][132]

    const int tid  = threadIdx.x;
    const int wid  = tid >> 5;
    const int lane = tid & 31;
    const int g    = lane >> 2;
    const int tig  = lane & 3;
    const int m0   = wid << 4;       // each warp owns 16 pixels

    const int bb  = blockIdx.x >> 9;
    const int hw0 = (blockIdx.x & 511) << 7;

    // ------- load this thread's 12 A-fragments directly from gmem -------
    // fragment kc: channels c0 = kc*16 + 2*tig (pairs), pixels p0 = m0+g, p0+8
    uint32_t af[12][4];
    {
        const float* xp = deg + (size_t)bb * 192 * 65536 + hw0 + m0 + g;
        #pragma unroll
        for (int kc = 0; kc < 12; kc++) {
            const float* q = xp + (size_t)(kc * 16 + 2 * tig) * 65536;
            af[kc][0] = pack_h2(q[0],                     q[(size_t)65536]);
            af[kc][1] = pack_h2(q[8],                     q[(size_t)65536 + 8]);
            af[kc][2] = pack_h2(q[(size_t)8 * 65536],     q[(size_t)9 * 65536]);
            af[kc][3] = pack_h2(q[(size_t)8 * 65536 + 8], q[(size_t)9 * 65536 + 8]);
        }
    }
    // per-thread b1 / W2 half2 pairs (index i = qt*2+nt -> pair j = i*4+tig)
    uint32_t b1r[8], w2r[8];
    #pragma unroll
    for (int i = 0; i < 8; i++) {
        float2 vb = __ldg((const float2*)(b1 + (i * 4 + tig) * 2));
        float2 vw = __ldg((const float2*)(W2 + (i * 4 + tig) * 2));
        b1r[i] = pack_h2(vb.x, vb.y);
        w2r[i] = pack_h2(vw.x, vw.y);
    }

    // -------- GEMM1 (fp16 MMA, fp16 acc) + half2 gating: full e per warp --------
    float spf[6][2] = {{0.f,0.f},{0.f,0.f},{0.f,0.f},{0.f,0.f},{0.f,0.f},{0.f,0.f}};
    #pragma unroll
    for (int qt = 0; qt < 4; qt++) {
        uint32_t accA[3][2][2], accC[3][2][2];
        #pragma unroll
        for (int t = 0; t < 3; t++)
            #pragma unroll
            for (int nt = 0; nt < 2; nt++) {
                const uint32_t bb1 = b1r[qt * 2 + nt];
                accA[t][nt][0] = 0u;  accA[t][nt][1] = 0u;
                accC[t][nt][0] = bb1; accC[t][nt][1] = bb1;   // fold +b1
            }

        #pragma unroll
        for (int kk = 0; kk < 4; kk++) {
            #pragma unroll
            for (int nt = 0; nt < 2; nt++) {
                const int ntA = qt * 2 + nt;
                uint2 av = __ldg((const uint2*)(g_w1h + ((kk * 16 + ntA) * 32 + lane) * 2));
                #pragma unroll
                for (int t = 0; t < 3; t++) mma16h(accA[t][nt], af[t * 4 + kk], av.x, av.y);
                const int ntC = 8 + qt * 2 + nt;
                uint2 cv = __ldg((const uint2*)(g_w1h + ((kk * 16 + ntC) * 32 + lane) * 2));
                #pragma unroll
                for (int t = 0; t < 3; t++) mma16h(accC[t][nt], af[t * 4 + kk], cv.x, cv.y);
            }
        }
        // half2 gating
        __half2 sph[6][2];
        #pragma unroll
        for (int q = 0; q < 6; q++)
            #pragma unroll
            for (int r = 0; r < 2; r++) sph[q][r] = __float2half2_rn(0.f);

        #pragma unroll
        for (int nt = 0; nt < 2; nt++) {
            const uint32_t w2u = w2r[qt * 2 + nt];
            const __half2 wv = *reinterpret_cast<const __half2*>(&w2u);
            #pragma unroll
            for (int r = 0; r < 2; r++) {
                __half2 A0 = *reinterpret_cast<__half2*>(&accA[0][nt][r]);
                __half2 A1 = *reinterpret_cast<__half2*>(&accA[1][nt][r]);
                __half2 A2 = *reinterpret_cast<__half2*>(&accA[2][nt][r]);
                __half2 C0 = *reinterpret_cast<__half2*>(&accC[0][nt][r]);
                __half2 C1 = *reinterpret_cast<__half2*>(&accC[1][nt][r]);
                __half2 C2 = *reinterpret_cast<__half2*>(&accC[2][nt][r]);
                sph[0][r] = gelu_w2_h2(__hadd2(A0, C1), wv, sph[0][r]);
                sph[1][r] = gelu_w2_h2(__hadd2(A0, C2), wv, sph[1][r]);
                sph[2][r] = gelu_w2_h2(__hadd2(A1, C0), wv, sph[2][r]);
                sph[3][r] = gelu_w2_h2(__hadd2(A1, C2), wv, sph[3][r]);
                sph[4][r] = gelu_w2_h2(__hadd2(A2, C0), wv, sph[4][r]);
                sph[5][r] = gelu_w2_h2(__hadd2(A2, C1), wv, sph[5][r]);
            }
        }
        #pragma unroll
        for (int q = 0; q < 6; q++)
            #pragma unroll
            for (int r = 0; r < 2; r++) {
                float2 f = __half22float2(sph[q][r]);
                spf[q][r] += f.x + f.y;
            }
    }
    // width-4 butterfly reduce + in-register sigmoid -> gate half2 broadcasts
    __half2 mh[2][6];   // [row][pair]
    {
        const float b2v = __ldg(b2);
        #pragma unroll
        for (int q = 0; q < 6; q++) {
            #pragma unroll
            for (int r = 0; r < 2; r++) {
                float v = spf[q][r];
                v += __shfl_xor_sync(0xffffffffu, v, 1, 4);
                v += __shfl_xor_sync(0xffffffffu, v, 2, 4);
                mh[r][q] = __float2half2_rn(sigmoid_t(v + b2v));
            }
        }
    }

    // -------- GEMM2 (fp16 MMA, fp32 acc): full k, full n per warp --------
    float D[8][4];
    #pragma unroll
    for (int n = 0; n < 8; n++)
        #pragma unroll
        for (int r = 0; r < 4; r++) D[n][r] = 0.f;

    #pragma unroll
    for (int dd = 0; dd < 4; dd++) {
        uint32_t yfa[3][4];
        #pragma unroll
        for (int t = 0; t < 3; t++) {
            const int u1 = (t == 0) ? 1 : 0;
            const int u2 = (t == 2) ? 1 : 2;
            #pragma unroll
            for (int r = 0; r < 4; r++) {
                const int row = r & 1;
                __half2 xt  = *reinterpret_cast<__half2*>(&af[t * 4 + dd][r]);
                __half2 xu1 = *reinterpret_cast<__half2*>(&af[u1 * 4 + dd][r]);
                __half2 xu2 = *reinterpret_cast<__half2*>(&af[u2 * 4 + dd][r]);
                __half2 y = __hfma2(mh[row][2 * t + 1], xu2,
                            __hfma2(mh[row][2 * t],     xu1, xt));
                yfa[t][r] = *reinterpret_cast<uint32_t*>(&y);
            }
        }
        #pragma unroll
        for (int t = 0; t < 3; t++) {
            const int kc = t * 4 + dd;
            #pragma unroll
            for (int n = 0; n < 8; n++) {
                uint2 bv = __ldg((const uint2*)(g_wfh + ((kc * 8 + n) * 32 + lane) * 2));
                mma16(D[n], yfa[t], bv.x, bv.y);
            }
        }
    }

    // -------- stage D into [64][132] for coalesced output --------
    #pragma unroll
    for (int n = 0; n < 8; n++) {
        #pragma unroll
        for (int cc = 0; cc < 2; cc++) {
            const int col = n * 8 + 2 * tig + cc;
            stg[col * STG_W + m0 + g]     = D[n][cc];
            stg[col * STG_W + m0 + g + 8] = D[n][2 + cc];
        }
    }
    __syncthreads();   // the ONLY block-wide barrier

    // -------- epilogue: stg + bf -> gmem (float4) --------
    {
        float* op = out + (size_t)bb * 64 * 65536 + hw0;
        #pragma unroll
        for (int i = tid; i < 64 * 32; i += THREADS) {
            int o = i >> 5, p4 = (i & 31) << 2;
            float4 v = *(const float4*)(stg + o * STG_W + p4);
            const float bfv = __ldg(bf + o);
            v.x += bfv; v.y += bfv; v.z += bfv; v.w += bfv;
            *(float4*)(op + (size_t)o * 65536 + p4) = v;
        }
    }
}

extern "C" void kernel_launch(void* const* d_in, const int* in_sizes, int n_in,
                              void* d_out, int out_size)
{
    const float* deg = (const float*)d_in[0];
    const float* W1  = (const float*)d_in[1];
    const float* b1  = (const float*)d_in[2];
    const float* W2  = (const float*)d_in[3];
    const float* b2  = (const float*)d_in[4];
    const float* Wf  = (const float*)d_in[5];
    const float* bf  = (const float*)d_in[6];
    float* outp = (float*)d_out;

    prep_w<<<20, 512>>>(W1, Wf);
    cudaFuncSetAttribute(dig_mma15, cudaFuncAttributeMaxDynamicSharedMemorySize, SM_BYTES);
    dig_mma15<<<NBLOCKS, THREADS, SM_BYTES>>>(deg, b1, W2, b2, bf, outp);
}